// round 5
// baseline (speedup 1.0000x reference)
#include <cuda_runtime.h>
#include <cuda_bf16.h>
#include <cstdint>

#define FULL_MASK 0xFFFFFFFFu
#define TAGS 32
#define START 30
#define STOP 31

__device__ float g_partial[2048];
__device__ int   g_count = 0;

typedef unsigned long long ull;

// ---- packed fp32x2 helpers (Blackwell FFMA2 path, full fp32 precision) ----
__device__ __forceinline__ ull pack2(float lo, float hi) {
    ull r; asm("mov.b64 %0, {%1, %2};" : "=l"(r) : "f"(lo), "f"(hi)); return r;
}
__device__ __forceinline__ void unpack2(float& lo, float& hi, ull v) {
    asm("mov.b64 {%0, %1}, %2;" : "=f"(lo), "=f"(hi) : "l"(v));
}
__device__ __forceinline__ ull fma2(ull a, ull b, ull c) {
    ull r; asm("fma.rn.f32x2 %0, %1, %2, %3;" : "=l"(r) : "l"(a), "l"(b), "l"(c)); return r;
}
__device__ __forceinline__ ull mul2(ull a, ull b) {
    ull r; asm("mul.rn.f32x2 %0, %1, %2;" : "=l"(r) : "l"(a), "l"(b)); return r;
}
__device__ __forceinline__ ull add2(ull a, ull b) {
    ull r; asm("add.rn.f32x2 %0, %1, %2;" : "=l"(r) : "l"(a), "l"(b)); return r;
}
__device__ __forceinline__ void lds_v2u64(ull& a, ull& b, uint32_t addr) {
    asm volatile("ld.shared.v2.u64 {%0, %1}, [%2];" : "=l"(a), "=l"(b) : "r"(addr));
}

// packed matvec body: 8x LDS.v2.u64 feeding 16 packed fma/mul, 7 packed adds
__device__ __forceinline__ float matvec32(uint32_t base, const ull* Ep) {
    ull c0, c1, c2, c3, c4, c5, c6, c7;
    ull qa, qb;
    lds_v2u64(qa, qb, base +   0); c0 = fma2(qb, Ep[ 1], mul2(qa, Ep[ 0]));
    lds_v2u64(qa, qb, base +  16); c1 = fma2(qb, Ep[ 3], mul2(qa, Ep[ 2]));
    lds_v2u64(qa, qb, base +  32); c2 = fma2(qb, Ep[ 5], mul2(qa, Ep[ 4]));
    lds_v2u64(qa, qb, base +  48); c3 = fma2(qb, Ep[ 7], mul2(qa, Ep[ 6]));
    lds_v2u64(qa, qb, base +  64); c4 = fma2(qb, Ep[ 9], mul2(qa, Ep[ 8]));
    lds_v2u64(qa, qb, base +  80); c5 = fma2(qb, Ep[11], mul2(qa, Ep[10]));
    lds_v2u64(qa, qb, base +  96); c6 = fma2(qb, Ep[13], mul2(qa, Ep[12]));
    lds_v2u64(qa, qb, base + 112); c7 = fma2(qb, Ep[15], mul2(qa, Ep[14]));
    ull d0 = add2(c0, c1), d1 = add2(c2, c3);
    ull d2 = add2(c4, c5), d3 = add2(c6, c7);
    ull g  = add2(add2(d0, d1), add2(d2, d3));
    float lo, hi;
    unpack2(lo, hi, g);
    return lo + hi;
}

// One block = one batch. Warp 0: forward recursion to m. Warp 1: backward
// recursion down to m. Combine: Z = sum_i alphaExp_m(i) * betaExp_m(i).
__global__ void __launch_bounds__(64, 16)
crf_nll_kernel(const float* __restrict__ feats,
               const float* __restrict__ trans,
               const int*   __restrict__ tags,
               const int*   __restrict__ lens,
               float* __restrict__ out,
               int B, int L)
{
    __shared__ __align__(16) float bufA[2][TAGS];   // forward ping-pong
    __shared__ __align__(16) float bufB[2][TAGS];   // backward ping-pong
    __shared__ __align__(16) float qout[TAGS];      // backward result q_m
    __shared__ float s_lsB;
    __shared__ float s_gold;

    int b    = blockIdx.x;
    int tid  = threadIdx.x;
    int wid  = tid >> 5;
    int lane = tid & 31;

    const float* fb = feats + (size_t)b * L * TAGS;
    const int*   tb = tags  + (size_t)b * L;
    int len = lens[b];
    int m   = (len - 1) >> 1;          // split point

    if (wid == 0) {
        // ================= FORWARD warp: alpha over feats[0..m] ============
        // lane j holds E column j packed: Ep[k] = (E[2k][j], E[2k+1][j])
        ull Ep[TAGS / 2];
#pragma unroll
        for (int k = 0; k < TAGS / 2; ++k) {
            float e0 = __expf(trans[(2 * k)     * TAGS + lane]);
            float e1 = __expf(trans[(2 * k + 1) * TAGS + lane]);
            Ep[k] = pack2(e0, e1);
        }

        float a0 = trans[START * TAGS + lane] + fb[lane];
        float mx = a0;
#pragma unroll
        for (int o = 16; o; o >>= 1) mx = fmaxf(mx, __shfl_xor_sync(FULL_MASK, mx, o));
        float p = __expf(a0 - mx);
        float lsA = mx;

        float q0 = (1 <= m) ? fb[1 * TAGS + lane] : 0.f;
        float q1 = (2 <= m) ? fb[2 * TAGS + lane] : 0.f;
        float q2 = (3 <= m) ? fb[3 * TAGS + lane] : 0.f;
        float q3 = (4 <= m) ? fb[4 * TAGS + lane] : 0.f;

        uint32_t sb = (uint32_t)__cvta_generic_to_shared(&bufA[0][0]);

#pragma unroll 4
        for (int t = 1; t <= m; ++t) {
            float f = __expf(q0);
            q0 = q1; q1 = q2; q2 = q3;
            q3 = (t + 4 <= m) ? fb[(t + 4) * TAGS + lane] : 0.f;

            int slot = t & 1;
            bufA[slot][lane] = p;
            __syncwarp();
            p = matvec32(sb + slot * (TAGS * 4), Ep) * f;

            if ((t & 3) == 0) {
                float m0 = __shfl_sync(FULL_MASK, p, 0);
                p *= (1.0f / m0);
                lsA += __logf(m0);
            }
        }

        // gold score (forward warp has <= half the steps; do gathers here)
        float midsum = 0.f;
        for (int t = lane; t < len - 1; t += 32) {
            int u = tb[t], w = tb[t + 1];
            midsum += trans[u * TAGS + w] + fb[(t + 1) * TAGS + w];
        }
#pragma unroll
        for (int o = 16; o; o >>= 1) midsum += __shfl_xor_sync(FULL_MASK, midsum, o);
        if (lane == 0) {
            int tag0 = tb[0];
            int tend = tb[len - 1];
            s_gold = trans[START * TAGS + tag0] + fb[tag0]
                   + trans[tend * TAGS + STOP] + midsum;
        }

        __syncthreads();   // backward result ready in qout / s_lsB

        // combine: Z = sum_i p(i) * q_m(i)
        float v = p * qout[lane];
#pragma unroll
        for (int o = 16; o; o >>= 1) v += __shfl_xor_sync(FULL_MASK, v, o);
        float fwd = lsA + s_lsB + __logf(v);

        if (lane == 0)
            g_partial[b] = fwd - s_gold;

        // fused deterministic final reduction (last block to finish)
        __threadfence();
        int old = 0;
        if (lane == 0) old = atomicAdd(&g_count, 1);
        old = __shfl_sync(FULL_MASK, old, 0);
        if (old == B - 1) {
            __threadfence();
            double acc = 0.0;
            for (int i = lane; i < B; i += 32)
                acc += (double)((volatile float*)g_partial)[i];
#pragma unroll
            for (int o = 16; o; o >>= 1)
                acc += __shfl_xor_sync(FULL_MASK, acc, o);
            if (lane == 0) {
                out[0] = (float)acc;
                g_count = 0;   // reset for next graph replay
            }
        }
    } else {
        // ================= BACKWARD warp: beta over feats[m+1..len-1] =======
        // lane i holds E row i packed: Ep[k] = (E[i][2k], E[i][2k+1])
        ull Ep[TAGS / 2];
#pragma unroll
        for (int k = 0; k < TAGS / 2; ++k) {
            float e0 = __expf(trans[lane * TAGS + 2 * k]);
            float e1 = __expf(trans[lane * TAGS + 2 * k + 1]);
            Ep[k] = pack2(e0, e1);
        }

        // beta_{len-1}(i) = trans[i][STOP]
        float q = __expf(trans[lane * TAGS + STOP]);
        float lsB = 0.f;

        int steps = (len - 1) - m;      // iterate t = len-2 down to m
        // prefetch ring over f_{t+1}: indices len-1, len-2, len-3, len-4
        float q0 = (len - 1 > m) ? fb[(len - 1) * TAGS + lane] : 0.f;
        float q1 = (len - 2 > m) ? fb[(len - 2) * TAGS + lane] : 0.f;
        float q2 = (len - 3 > m) ? fb[(len - 3) * TAGS + lane] : 0.f;
        float q3 = (len - 4 > m) ? fb[(len - 4) * TAGS + lane] : 0.f;

        uint32_t sb = (uint32_t)__cvta_generic_to_shared(&bufB[0][0]);

#pragma unroll 4
        for (int s = 0; s < steps; ++s) {
            float f = __expf(q0);
            q0 = q1; q1 = q2; q2 = q3;
            int idx = len - 5 - s;      // next prefetch index (t+1 four ahead)
            q3 = (idx > m) ? fb[idx * TAGS + lane] : 0.f;

            float r = q * f;            // r_j = q_j * exp(f_{t+1,j})
            int slot = s & 1;
            bufB[slot][lane] = r;
            __syncwarp();
            q = matvec32(sb + slot * (TAGS * 4), Ep);

            if ((s & 3) == 3) {
                float m0 = __shfl_sync(FULL_MASK, q, 0);
                q *= (1.0f / m0);
                lsB += __logf(m0);
            }
        }

        qout[lane] = q;
        if (lane == 0) s_lsB = lsB;
        __syncthreads();
        // warp 0 finishes the combine + reduction
    }
}

extern "C" void kernel_launch(void* const* d_in, const int* in_sizes, int n_in,
                              void* d_out, int out_size)
{
    const float* feats = (const float*)d_in[0];
    const float* trans = (const float*)d_in[1];
    const int*   tags  = (const int*)d_in[2];
    const int*   lens  = (const int*)d_in[3];
    float* out = (float*)d_out;

    int B = in_sizes[3];                  // word_seq_lens: (B,)
    int L = in_sizes[2] / B;              // tags: (B, L)

    crf_nll_kernel<<<B, 64>>>(feats, trans, tags, lens, out, B, L);
}

// round 6
// speedup vs baseline: 1.3216x; 1.3216x over previous
#include <cuda_runtime.h>
#include <cuda_bf16.h>
#include <cstdint>

#define FULL_MASK 0xFFFFFFFFu
#define TAGS 32
#define START 30
#define STOP 31

__device__ float g_partial[2048];
__device__ int   g_count = 0;

typedef unsigned long long ull;

// ---- packed fp32x2 helpers (Blackwell FFMA2 path, full fp32 precision) ----
__device__ __forceinline__ ull pack2(float lo, float hi) {
    ull r; asm("mov.b64 %0, {%1, %2};" : "=l"(r) : "f"(lo), "f"(hi)); return r;
}
__device__ __forceinline__ void unpack2(float& lo, float& hi, ull v) {
    asm("mov.b64 {%0, %1}, %2;" : "=f"(lo), "=f"(hi) : "l"(v));
}
__device__ __forceinline__ ull fma2(ull a, ull b, ull c) {
    ull r; asm("fma.rn.f32x2 %0, %1, %2, %3;" : "=l"(r) : "l"(a), "l"(b), "l"(c)); return r;
}
__device__ __forceinline__ ull mul2(ull a, ull b) {
    ull r; asm("mul.rn.f32x2 %0, %1, %2;" : "=l"(r) : "l"(a), "l"(b)); return r;
}
__device__ __forceinline__ ull add2(ull a, ull b) {
    ull r; asm("add.rn.f32x2 %0, %1, %2;" : "=l"(r) : "l"(a), "l"(b)); return r;
}
__device__ __forceinline__ void lds_v2u64(ull& a, ull& b, uint32_t addr) {
    asm volatile("ld.shared.v2.u64 {%0, %1}, [%2];" : "=l"(a), "=l"(b) : "r"(addr));
}

// packed matvec body: 8x LDS.v2.u64 feeding 16 packed fma/mul, 7 packed adds
__device__ __forceinline__ float matvec32(uint32_t base, const ull* Ep) {
    ull c0, c1, c2, c3, c4, c5, c6, c7;
    ull qa, qb;
    lds_v2u64(qa, qb, base +   0); c0 = fma2(qb, Ep[ 1], mul2(qa, Ep[ 0]));
    lds_v2u64(qa, qb, base +  16); c1 = fma2(qb, Ep[ 3], mul2(qa, Ep[ 2]));
    lds_v2u64(qa, qb, base +  32); c2 = fma2(qb, Ep[ 5], mul2(qa, Ep[ 4]));
    lds_v2u64(qa, qb, base +  48); c3 = fma2(qb, Ep[ 7], mul2(qa, Ep[ 6]));
    lds_v2u64(qa, qb, base +  64); c4 = fma2(qb, Ep[ 9], mul2(qa, Ep[ 8]));
    lds_v2u64(qa, qb, base +  80); c5 = fma2(qb, Ep[11], mul2(qa, Ep[10]));
    lds_v2u64(qa, qb, base +  96); c6 = fma2(qb, Ep[13], mul2(qa, Ep[12]));
    lds_v2u64(qa, qb, base + 112); c7 = fma2(qb, Ep[15], mul2(qa, Ep[14]));
    ull d0 = add2(c0, c1), d1 = add2(c2, c3);
    ull d2 = add2(c4, c5), d3 = add2(c6, c7);
    ull g  = add2(add2(d0, d1), add2(d2, d3));
    float lo, hi;
    unpack2(lo, hi, g);
    return lo + hi;
}

// One block = one batch. Warp 0: forward recursion to m. Warp 1: backward
// recursion down to m. Combine: Z = sum_i alphaExp_m(i) * betaExp_m(i).
// launch_bounds(64, 8): 128 regs/thread so Ep[16] (32 regs) stays resident.
__global__ void __launch_bounds__(64, 8)
crf_nll_kernel(const float* __restrict__ feats,
               const float* __restrict__ trans,
               const int*   __restrict__ tags,
               const int*   __restrict__ lens,
               float* __restrict__ out,
               int B, int L)
{
    __shared__ __align__(16) float bufA[2][TAGS];   // forward ping-pong
    __shared__ __align__(16) float bufB[2][TAGS];   // backward ping-pong
    __shared__ __align__(16) float qout[TAGS];      // backward result q_m
    __shared__ float s_lsB;
    __shared__ float s_gold;

    int b    = blockIdx.x;
    int tid  = threadIdx.x;
    int wid  = tid >> 5;
    int lane = tid & 31;

    const float* fb = feats + (size_t)b * L * TAGS;
    const int*   tb = tags  + (size_t)b * L;
    int len = lens[b];
    int m   = (len - 1) >> 1;          // split point

    if (wid == 0) {
        // ================= FORWARD warp: alpha over feats[0..m] ============
        // lane j holds E column j packed: Ep[k] = (E[2k][j], E[2k+1][j])
        ull Ep[TAGS / 2];
#pragma unroll
        for (int k = 0; k < TAGS / 2; ++k) {
            float e0 = __expf(trans[(2 * k)     * TAGS + lane]);
            float e1 = __expf(trans[(2 * k + 1) * TAGS + lane]);
            Ep[k] = pack2(e0, e1);
        }

        float a0 = trans[START * TAGS + lane] + fb[lane];
        float mx = a0;
#pragma unroll
        for (int o = 16; o; o >>= 1) mx = fmaxf(mx, __shfl_xor_sync(FULL_MASK, mx, o));
        float p = __expf(a0 - mx);
        float lsA = mx;

        float q0 = (1 <= m) ? fb[1 * TAGS + lane] : 0.f;
        float q1 = (2 <= m) ? fb[2 * TAGS + lane] : 0.f;
        float q2 = (3 <= m) ? fb[3 * TAGS + lane] : 0.f;
        float q3 = (4 <= m) ? fb[4 * TAGS + lane] : 0.f;

        uint32_t sb = (uint32_t)__cvta_generic_to_shared(&bufA[0][0]);

#pragma unroll 4
        for (int t = 1; t <= m; ++t) {
            float f = __expf(q0);
            q0 = q1; q1 = q2; q2 = q3;
            q3 = (t + 4 <= m) ? fb[(t + 4) * TAGS + lane] : 0.f;

            int slot = t & 1;
            bufA[slot][lane] = p;
            __syncwarp();
            p = matvec32(sb + slot * (TAGS * 4), Ep) * f;

            if ((t & 3) == 0) {
                float m0 = __shfl_sync(FULL_MASK, p, 0);
                p *= (1.0f / m0);
                lsA += __logf(m0);
            }
        }

        // gold score (forward warp has <= half the steps; do gathers here)
        float midsum = 0.f;
        for (int t = lane; t < len - 1; t += 32) {
            int u = tb[t], w = tb[t + 1];
            midsum += trans[u * TAGS + w] + fb[(t + 1) * TAGS + w];
        }
#pragma unroll
        for (int o = 16; o; o >>= 1) midsum += __shfl_xor_sync(FULL_MASK, midsum, o);
        if (lane == 0) {
            int tag0 = tb[0];
            int tend = tb[len - 1];
            s_gold = trans[START * TAGS + tag0] + fb[tag0]
                   + trans[tend * TAGS + STOP] + midsum;
        }

        __syncthreads();   // backward result ready in qout / s_lsB

        // combine: Z = sum_i p(i) * q_m(i)
        float v = p * qout[lane];
#pragma unroll
        for (int o = 16; o; o >>= 1) v += __shfl_xor_sync(FULL_MASK, v, o);
        float fwd = lsA + s_lsB + __logf(v);

        if (lane == 0)
            g_partial[b] = fwd - s_gold;

        // fused deterministic final reduction (last block to finish)
        __threadfence();
        int old = 0;
        if (lane == 0) old = atomicAdd(&g_count, 1);
        old = __shfl_sync(FULL_MASK, old, 0);
        if (old == B - 1) {
            __threadfence();
            double acc = 0.0;
            for (int i = lane; i < B; i += 32)
                acc += (double)((volatile float*)g_partial)[i];
#pragma unroll
            for (int o = 16; o; o >>= 1)
                acc += __shfl_xor_sync(FULL_MASK, acc, o);
            if (lane == 0) {
                out[0] = (float)acc;
                g_count = 0;   // reset for next graph replay
            }
        }
    } else {
        // ================= BACKWARD warp: beta over feats[m+1..len-1] =======
        // lane i holds E row i packed: Ep[k] = (E[i][2k], E[i][2k+1])
        ull Ep[TAGS / 2];
#pragma unroll
        for (int k = 0; k < TAGS / 2; ++k) {
            float e0 = __expf(trans[lane * TAGS + 2 * k]);
            float e1 = __expf(trans[lane * TAGS + 2 * k + 1]);
            Ep[k] = pack2(e0, e1);
        }

        // beta_{len-1}(i) = trans[i][STOP]
        float q = __expf(trans[lane * TAGS + STOP]);
        float lsB = 0.f;

        int steps = (len - 1) - m;      // iterate t = len-2 down to m
        // prefetch ring over f_{t+1}: indices len-1, len-2, len-3, len-4
        float q0 = (len - 1 > m) ? fb[(len - 1) * TAGS + lane] : 0.f;
        float q1 = (len - 2 > m) ? fb[(len - 2) * TAGS + lane] : 0.f;
        float q2 = (len - 3 > m) ? fb[(len - 3) * TAGS + lane] : 0.f;
        float q3 = (len - 4 > m) ? fb[(len - 4) * TAGS + lane] : 0.f;

        uint32_t sb = (uint32_t)__cvta_generic_to_shared(&bufB[0][0]);

#pragma unroll 4
        for (int s = 0; s < steps; ++s) {
            float f = __expf(q0);
            q0 = q1; q1 = q2; q2 = q3;
            int idx = len - 5 - s;      // next prefetch index (t+1 four ahead)
            q3 = (idx > m) ? fb[idx * TAGS + lane] : 0.f;

            float r = q * f;            // r_j = q_j * exp(f_{t+1,j})
            int slot = s & 1;
            bufB[slot][lane] = r;
            __syncwarp();
            q = matvec32(sb + slot * (TAGS * 4), Ep);

            if ((s & 3) == 3) {
                float m0 = __shfl_sync(FULL_MASK, q, 0);
                q *= (1.0f / m0);
                lsB += __logf(m0);
            }
        }

        qout[lane] = q;
        if (lane == 0) s_lsB = lsB;
        __syncthreads();
        // warp 0 finishes the combine + reduction
    }
}

extern "C" void kernel_launch(void* const* d_in, const int* in_sizes, int n_in,
                              void* d_out, int out_size)
{
    const float* feats = (const float*)d_in[0];
    const float* trans = (const float*)d_in[1];
    const int*   tags  = (const int*)d_in[2];
    const int*   lens  = (const int*)d_in[3];
    float* out = (float*)d_out;

    int B = in_sizes[3];                  // word_seq_lens: (B,)
    int L = in_sizes[2] / B;              // tags: (B, L)

    crf_nll_kernel<<<B, 64>>>(feats, trans, tags, lens, out, B, L);
}

// round 7
// speedup vs baseline: 1.3282x; 1.0050x over previous
#include <cuda_runtime.h>
#include <cuda_bf16.h>
#include <cstdint>

#define FULL_MASK 0xFFFFFFFFu
#define TAGS 32
#define START 30
#define STOP 31

__device__ float g_partial[2048];
__device__ int   g_count = 0;

typedef unsigned long long ull;

// ---- packed fp32x2 helpers (Blackwell FFMA2 path, full fp32 precision) ----
__device__ __forceinline__ ull pack2(float lo, float hi) {
    ull r; asm("mov.b64 %0, {%1, %2};" : "=l"(r) : "f"(lo), "f"(hi)); return r;
}
__device__ __forceinline__ void unpack2(float& lo, float& hi, ull v) {
    asm("mov.b64 {%0, %1}, %2;" : "=f"(lo), "=f"(hi) : "l"(v));
}
__device__ __forceinline__ ull fma2(ull a, ull b, ull c) {
    ull r; asm("fma.rn.f32x2 %0, %1, %2, %3;" : "=l"(r) : "l"(a), "l"(b), "l"(c)); return r;
}
__device__ __forceinline__ ull mul2(ull a, ull b) {
    ull r; asm("mul.rn.f32x2 %0, %1, %2;" : "=l"(r) : "l"(a), "l"(b)); return r;
}
__device__ __forceinline__ ull add2(ull a, ull b) {
    ull r; asm("add.rn.f32x2 %0, %1, %2;" : "=l"(r) : "l"(a), "l"(b)); return r;
}
__device__ __forceinline__ void lds_v2u64(ull& a, ull& b, uint32_t addr) {
    asm volatile("ld.shared.v2.u64 {%0, %1}, [%2];" : "=l"(a), "=l"(b) : "r"(addr));
}

// packed matvec body: 8x LDS.v2.u64 feeding 16 packed fma/mul, 7 packed adds
__device__ __forceinline__ float matvec32(uint32_t base, const ull* Ep) {
    ull c0, c1, c2, c3, c4, c5, c6, c7;
    ull qa, qb;
    lds_v2u64(qa, qb, base +   0); c0 = fma2(qb, Ep[ 1], mul2(qa, Ep[ 0]));
    lds_v2u64(qa, qb, base +  16); c1 = fma2(qb, Ep[ 3], mul2(qa, Ep[ 2]));
    lds_v2u64(qa, qb, base +  32); c2 = fma2(qb, Ep[ 5], mul2(qa, Ep[ 4]));
    lds_v2u64(qa, qb, base +  48); c3 = fma2(qb, Ep[ 7], mul2(qa, Ep[ 6]));
    lds_v2u64(qa, qb, base +  64); c4 = fma2(qb, Ep[ 9], mul2(qa, Ep[ 8]));
    lds_v2u64(qa, qb, base +  80); c5 = fma2(qb, Ep[11], mul2(qa, Ep[10]));
    lds_v2u64(qa, qb, base +  96); c6 = fma2(qb, Ep[13], mul2(qa, Ep[12]));
    lds_v2u64(qa, qb, base + 112); c7 = fma2(qb, Ep[15], mul2(qa, Ep[14]));
    ull d0 = add2(c0, c1), d1 = add2(c2, c3);
    ull d2 = add2(c4, c5), d3 = add2(c6, c7);
    ull g  = add2(add2(d0, d1), add2(d2, d3));
    float lo, hi;
    unpack2(lo, hi, g);
    return lo + hi;
}

// One block = one batch. Warp 0: forward recursion to m. Warp 1: backward
// recursion down to m. Combine: Z = sum_i alphaExp_m(i) * betaExp_m(i).
// Renorm is pipelined: sample (phase 0) -> rcp/log (phase 1) -> apply (phase 3),
// so only one FMUL per 4 steps sits on the serial p-chain. The scale constant
// is 3 steps stale, which is exact (any positive constant works) and keeps
// the max exponent between applies < ~78, safely inside fp32 range.
__global__ void __launch_bounds__(64, 8)
crf_nll_kernel(const float* __restrict__ feats,
               const float* __restrict__ trans,
               const int*   __restrict__ tags,
               const int*   __restrict__ lens,
               float* __restrict__ out,
               int B, int L)
{
    __shared__ __align__(16) float bufA[2][TAGS];   // forward ping-pong
    __shared__ __align__(16) float bufB[2][TAGS];   // backward ping-pong
    __shared__ __align__(16) float qout[TAGS];      // backward result q_m
    __shared__ float s_lsB;
    __shared__ float s_goldB;

    int b    = blockIdx.x;
    int tid  = threadIdx.x;
    int wid  = tid >> 5;
    int lane = tid & 31;

    const float* fb = feats + (size_t)b * L * TAGS;
    const int*   tb = tags  + (size_t)b * L;
    int len = lens[b];
    int m   = (len - 1) >> 1;          // split point

    if (wid == 0) {
        // ================= FORWARD warp: alpha over feats[0..m] ============
        // lane j holds E column j packed: Ep[k] = (E[2k][j], E[2k+1][j])
        ull Ep[TAGS / 2];
#pragma unroll
        for (int k = 0; k < TAGS / 2; ++k) {
            float e0 = __expf(trans[(2 * k)     * TAGS + lane]);
            float e1 = __expf(trans[(2 * k + 1) * TAGS + lane]);
            Ep[k] = pack2(e0, e1);
        }

        float a0 = trans[START * TAGS + lane] + fb[lane];
        float mx = a0;
#pragma unroll
        for (int o = 16; o; o >>= 1) mx = fmaxf(mx, __shfl_xor_sync(FULL_MASK, mx, o));
        float p = __expf(a0 - mx);
        float lsA = mx;

        float q0 = (1 <= m) ? fb[1 * TAGS + lane] : 0.f;
        float q1 = (2 <= m) ? fb[2 * TAGS + lane] : 0.f;
        float q2 = (3 <= m) ? fb[3 * TAGS + lane] : 0.f;
        float q3 = (4 <= m) ? fb[4 * TAGS + lane] : 0.f;

        uint32_t sb = (uint32_t)__cvta_generic_to_shared(&bufA[0][0]);

        // pipelined renorm state
        float m0 = 1.0f, rr = 1.0f, lg = 0.0f;

#pragma unroll 4
        for (int t = 1; t <= m; ++t) {
            float f = __expf(q0);
            q0 = q1; q1 = q2; q2 = q3;
            q3 = (t + 4 <= m) ? fb[(t + 4) * TAGS + lane] : 0.f;

            int slot = t & 1;
            bufA[slot][lane] = p;
            __syncwarp();
            p = matvec32(sb + slot * (TAGS * 4), Ep) * f;

            int ph = t & 3;
            if (ph == 0) {
                m0 = __shfl_sync(FULL_MASK, p, 0);        // sample (off-chain use)
            } else if (ph == 1) {
                rr = __fdividef(1.0f, m0);                // fast rcp, off-chain
                lg = __logf(m0);
            } else if (ph == 3) {
                p *= rr;                                  // only on-chain op
                lsA += lg;
            }
        }

        // gold score: forward warp gathers t in [0, m)
        float midsum = 0.f;
        for (int t = lane; t < m; t += 32) {
            int u = tb[t], w = tb[t + 1];
            midsum += trans[u * TAGS + w] + fb[(t + 1) * TAGS + w];
        }
#pragma unroll
        for (int o = 16; o; o >>= 1) midsum += __shfl_xor_sync(FULL_MASK, midsum, o);

        __syncthreads();   // backward result ready in qout / s_lsB / s_goldB

        // combine: Z = sum_i p(i) * q_m(i)
        float v = p * qout[lane];
#pragma unroll
        for (int o = 16; o; o >>= 1) v += __shfl_xor_sync(FULL_MASK, v, o);
        float fwd = lsA + s_lsB + __logf(v);

        if (lane == 0) {
            int tag0 = tb[0];
            int tend = tb[len - 1];
            float gold = trans[START * TAGS + tag0] + fb[tag0]
                       + trans[tend * TAGS + STOP] + midsum + s_goldB;
            g_partial[b] = fwd - gold;
        }

        // fused deterministic final reduction (last block to finish)
        __threadfence();
        int old = 0;
        if (lane == 0) old = atomicAdd(&g_count, 1);
        old = __shfl_sync(FULL_MASK, old, 0);
        if (old == B - 1) {
            __threadfence();
            double acc = 0.0;
            for (int i = lane; i < B; i += 32)
                acc += (double)((volatile float*)g_partial)[i];
#pragma unroll
            for (int o = 16; o; o >>= 1)
                acc += __shfl_xor_sync(FULL_MASK, acc, o);
            if (lane == 0) {
                out[0] = (float)acc;
                g_count = 0;   // reset for next graph replay
            }
        }
    } else {
        // ================= BACKWARD warp: beta over feats[m+1..len-1] =======
        // lane i holds E row i packed: Ep[k] = (E[i][2k], E[i][2k+1])
        ull Ep[TAGS / 2];
#pragma unroll
        for (int k = 0; k < TAGS / 2; ++k) {
            float e0 = __expf(trans[lane * TAGS + 2 * k]);
            float e1 = __expf(trans[lane * TAGS + 2 * k + 1]);
            Ep[k] = pack2(e0, e1);
        }

        // beta_{len-1}(i) = trans[i][STOP]
        float q = __expf(trans[lane * TAGS + STOP]);
        float lsB = 0.f;

        int steps = (len - 1) - m;      // iterate t = len-2 down to m
        // prefetch ring over f_{t+1}: indices len-1, len-2, len-3, len-4
        float q0 = (len - 1 > m) ? fb[(len - 1) * TAGS + lane] : 0.f;
        float q1 = (len - 2 > m) ? fb[(len - 2) * TAGS + lane] : 0.f;
        float q2 = (len - 3 > m) ? fb[(len - 3) * TAGS + lane] : 0.f;
        float q3 = (len - 4 > m) ? fb[(len - 4) * TAGS + lane] : 0.f;

        uint32_t sb = (uint32_t)__cvta_generic_to_shared(&bufB[0][0]);

        // pipelined renorm state
        float m0 = 1.0f, rr = 1.0f, lg = 0.0f;

#pragma unroll 4
        for (int s = 0; s < steps; ++s) {
            float f = __expf(q0);
            q0 = q1; q1 = q2; q2 = q3;
            int idx = len - 5 - s;      // next prefetch index (t+1 four ahead)
            q3 = (idx > m) ? fb[idx * TAGS + lane] : 0.f;

            float r = q * f;            // r_j = q_j * exp(f_{t+1,j})
            int slot = s & 1;
            bufB[slot][lane] = r;
            __syncwarp();
            q = matvec32(sb + slot * (TAGS * 4), Ep);

            int ph = s & 3;
            if (ph == 0) {
                m0 = __shfl_sync(FULL_MASK, q, 0);
            } else if (ph == 1) {
                rr = __fdividef(1.0f, m0);
                lg = __logf(m0);
            } else if (ph == 3) {
                q *= rr;
                lsB += lg;
            }
        }

        // gold score: backward warp gathers t in [m, len-1)
        float midsum = 0.f;
        for (int t = m + lane; t < len - 1; t += 32) {
            int u = tb[t], w = tb[t + 1];
            midsum += trans[u * TAGS + w] + fb[(t + 1) * TAGS + w];
        }
#pragma unroll
        for (int o = 16; o; o >>= 1) midsum += __shfl_xor_sync(FULL_MASK, midsum, o);

        qout[lane] = q;
        if (lane == 0) {
            s_lsB = lsB;
            s_goldB = midsum;
        }
        __syncthreads();
        // warp 0 finishes the combine + reduction
    }
}

extern "C" void kernel_launch(void* const* d_in, const int* in_sizes, int n_in,
                              void* d_out, int out_size)
{
    const float* feats = (const float*)d_in[0];
    const float* trans = (const float*)d_in[1];
    const int*   tags  = (const int*)d_in[2];
    const int*   lens  = (const int*)d_in[3];
    float* out = (float*)d_out;

    int B = in_sizes[3];                  // word_seq_lens: (B,)
    int L = in_sizes[2] / B;              // tags: (B, L)

    crf_nll_kernel<<<B, 64>>>(feats, trans, tags, lens, out, B, L);
}